// round 16
// baseline (speedup 1.0000x reference)
#include <cuda_runtime.h>
#include <cuda_fp16.h>
#include <math.h>
#include <stdint.h>

#define NH   16
#define DKH  64
#define DM   1024
#define NB   2
#define SEQ  2048
#define MTOK (NB * SEQ)   // 4096

// ---------------------------------------------------------------------------
// Device scratch
// ---------------------------------------------------------------------------
__device__ __half g_xhi[(size_t)3 * MTOK * DM];
__device__ __half g_xlo[(size_t)3 * MTOK * DM];
__device__ __half g_whi[(size_t)4 * DM * DM];

__device__ __half g_qhi[(size_t)MTOK * DM];
__device__ __half g_qlo[(size_t)MTOK * DM];
__device__ __half g_khi[(size_t)MTOK * DM];
__device__ __half g_vhi[(size_t)MTOK * DM];

__device__ __half g_chi[(size_t)MTOK * DM];
__device__ __half g_clo[(size_t)MTOK * DM];

// ---------------------------------------------------------------------------
// PTX helpers
// ---------------------------------------------------------------------------
__device__ __forceinline__ uint32_t smem_u32(const void* p) {
    uint32_t a;
    asm("{ .reg .u64 t; cvta.to.shared.u64 t, %1; cvt.u32.u64 %0, t; }" : "=r"(a) : "l"(p));
    return a;
}
__device__ __forceinline__ void cp_async16(uint32_t dst, const void* src) {
    asm volatile("cp.async.cg.shared.global [%0], [%1], 16;" :: "r"(dst), "l"(src));
}
__device__ __forceinline__ void cp_commit() {
    asm volatile("cp.async.commit_group;");
}
__device__ __forceinline__ void cp_wait0() {
    asm volatile("cp.async.wait_group 0;");
}
__device__ __forceinline__ void cp_wait1() {
    asm volatile("cp.async.wait_group 1;");
}
__device__ __forceinline__ void ldsm4(uint32_t* r, uint32_t addr) {
    asm volatile("ldmatrix.sync.aligned.m8n8.x4.shared.b16 {%0,%1,%2,%3}, [%4];"
                 : "=r"(r[0]), "=r"(r[1]), "=r"(r[2]), "=r"(r[3]) : "r"(addr));
}
__device__ __forceinline__ void ldsm4t(uint32_t* r, uint32_t addr) {
    asm volatile("ldmatrix.sync.aligned.m8n8.x4.trans.shared.b16 {%0,%1,%2,%3}, [%4];"
                 : "=r"(r[0]), "=r"(r[1]), "=r"(r[2]), "=r"(r[3]) : "r"(addr));
}
__device__ __forceinline__ void mma16816(float* c, const uint32_t* a, const uint32_t* b) {
    asm volatile(
        "mma.sync.aligned.m16n8k16.row.col.f32.f16.f16.f32 "
        "{%0,%1,%2,%3}, {%4,%5,%6,%7}, {%8,%9}, {%0,%1,%2,%3};"
        : "+f"(c[0]), "+f"(c[1]), "+f"(c[2]), "+f"(c[3])
        : "r"(a[0]), "r"(a[1]), "r"(a[2]), "r"(a[3]), "r"(b[0]), "r"(b[1]));
}
__device__ __forceinline__ float ex2f(float x) {
    float y;
    asm("ex2.approx.f32 %0, %1;" : "=f"(y) : "f"(x));
    return y;
}
__device__ __forceinline__ uint32_t ex2_h2(uint32_t x) {
    uint32_t y;
    asm("ex2.approx.f16x2 %0, %1;" : "=r"(y) : "r"(x));
    return y;
}
__device__ __forceinline__ uint32_t h2u(__half2 h) {
    return *reinterpret_cast<uint32_t*>(&h);
}
// SW128 swizzle for 128-byte rows
__device__ __forceinline__ uint32_t swz128(uint32_t off) {
    return off ^ (((off >> 7) & 7u) << 4);
}

// ---------------------------------------------------------------------------
// Fused conversions: 3 split (q,k,v) + 4 tohalf (W) in one launch
// ---------------------------------------------------------------------------
struct ConvArgs {
    const float *x0, *x1, *x2;
    const float *w0, *w1, *w2, *w3;
    __half *xhi, *xlo, *whi;
};

#define XQ4 ((size_t)MTOK * DM / 4)
#define WQ4 ((size_t)DM * DM / 4)
#define CONV_TOTAL (3 * 1048576 + 4 * 262144)

__global__ __launch_bounds__(256) void convert_all(ConvArgs a) {
    size_t i = (size_t)blockIdx.x * 256 + threadIdx.x;
    if (i < 3 * XQ4) {
        int which = (int)(i / XQ4);
        size_t off = i - (size_t)which * XQ4;
        const float* src = (which == 0) ? a.x0 : ((which == 1) ? a.x1 : a.x2);
        float4 v = ((const float4*)src)[off];
        size_t o = (size_t)which * XQ4 + off;
        __half2 h0 = __floats2half2_rn(v.x, v.y);
        __half2 h1 = __floats2half2_rn(v.z, v.w);
        float2 f0 = __half22float2(h0);
        float2 f1 = __half22float2(h1);
        ((__half2*)a.xhi)[2 * o]     = h0;
        ((__half2*)a.xhi)[2 * o + 1] = h1;
        ((__half2*)a.xlo)[2 * o]     = __floats2half2_rn(v.x - f0.x, v.y - f0.y);
        ((__half2*)a.xlo)[2 * o + 1] = __floats2half2_rn(v.z - f1.x, v.w - f1.y);
    } else {
        size_t j = i - 3 * XQ4;
        int which = (int)(j / WQ4);
        size_t off = j - (size_t)which * WQ4;
        const float* src = (which == 0) ? a.w0 : ((which == 1) ? a.w1 : ((which == 2) ? a.w2 : a.w3));
        float4 v = ((const float4*)src)[off];
        size_t o = (size_t)which * WQ4 + off;
        ((__half2*)a.whi)[2 * o]     = __floats2half2_rn(v.x, v.y);
        ((__half2*)a.whi)[2 * o + 1] = __floats2half2_rn(v.z, v.w);
    }
}

// ---------------------------------------------------------------------------
// mma.sync GEMM (NT): C = A[M,K]*W[N,K]^T + bias; A split (hi+lo), W fp16.
// 128x128 tile, BK=64, 2-stage cp.async double buffer, 1 sync/chunk, 2 CTAs/SM.
// ---------------------------------------------------------------------------
struct GemmArgs {
    const __half *xhi, *xlo, *whi;
    const float *b0, *b1, *b2;
    float *o0, *o1, *o2;                      // fp32 outputs (NULL => half mode)
    __half *ohi0, *olo0, *ohi1, *olo1, *ohi2, *olo2;
    float s0, s1, s2;
    long long xstride, wstride;
};

#define GTILE_B  16384                 // 128 rows x 64 halfs (128B rows)
#define GSTAGE_B (3 * GTILE_B)         // Ahi, Alo, Whi = 48 KB
#define GEMM_SMEM (2 * GSTAGE_B)       // 96 KB
#define NCHUNK   (DM / 64)             // 16

__global__ __launch_bounds__(256, 2) void gemm_tc(GemmArgs ar) {
    extern __shared__ char sm[];
    const uint32_t sbase = smem_u32(sm);

    const int tid = threadIdx.x;
    const int wid = tid >> 5;
    const int lid = tid & 31;
    const int z = blockIdx.z;

    const __half* xhi = ar.xhi + (size_t)z * ar.xstride;
    const __half* xlo = ar.xlo + (size_t)z * ar.xstride;
    const __half* whi = ar.whi + (size_t)z * ar.wstride;
    const float* bias = (z == 0) ? ar.b0 : ((z == 1) ? ar.b1 : ar.b2);
    const float scale = (z == 0) ? ar.s0 : ((z == 1) ? ar.s1 : ar.s2);

    const int bm = blockIdx.y * 128;
    const int bn = blockIdx.x * 128;

    // loader: each thread does 4 segments per tile (rows baserow+32i, seg sg)
    const int baserow = tid >> 3;      // 0..31
    const int sg = tid & 7;            // 16B segment within 128B row
    const __half* pA = xhi + (size_t)(bm + baserow) * DM + sg * 8;
    const __half* pL = xlo + (size_t)(bm + baserow) * DM + sg * 8;
    const __half* pW = whi + (size_t)(bn + baserow) * DM + sg * 8;
    uint32_t so[4];
#pragma unroll
    for (int i = 0; i < 4; i++)
        so[i] = swz128((uint32_t)((baserow + 32 * i) * 128 + sg * 16));

    auto load_stage = [&](int chunk, int stage) {
        const int k0 = chunk * 64;
        const uint32_t st = sbase + stage * GSTAGE_B;
#pragma unroll
        for (int i = 0; i < 4; i++) {
            const size_t g = (size_t)(32 * i) * DM + k0;
            cp_async16(st + so[i],               pA + g);
            cp_async16(st + GTILE_B + so[i],     pL + g);
            cp_async16(st + 2 * GTILE_B + so[i], pW + g);
        }
    };

    const int wm = wid & 3;
    const int wn = wid >> 2;
    const int lm_row = (lid & 7) + 8 * ((lid >> 3) & 1);
    const uint32_t lsw = ((uint32_t)(lm_row & 7)) << 4;
    const uint32_t cpick = (uint32_t)(16 * (lid >> 4));

    uint32_t arow[2], wrow[4];
#pragma unroll
    for (int mi = 0; mi < 2; mi++)
        arow[mi] = (uint32_t)((wm * 32 + mi * 16 + lm_row) * 128);
#pragma unroll
    for (int j = 0; j < 4; j++)
        wrow[j] = (uint32_t)((wn * 64 + j * 16 + lm_row) * 128);

    float acc[2][8][4];
#pragma unroll
    for (int i = 0; i < 2; i++)
#pragma unroll
        for (int j = 0; j < 8; j++)
#pragma unroll
            for (int k = 0; k < 4; k++) acc[i][j][k] = 0.0f;

    load_stage(0, 0); cp_commit();

    for (int c = 0; c < NCHUNK; c++) {
        cp_wait0();
        __syncthreads();   // stage c data visible; compute(c-1) done block-wide
        if (c + 1 < NCHUNK) { load_stage(c + 1, (c + 1) & 1); cp_commit(); }

        const uint32_t st = sbase + (uint32_t)(c & 1) * GSTAGE_B;

#pragma unroll
        for (int kg = 0; kg < 4; kg++) {
            const uint32_t cb = (cpick + kg * 32) ^ lsw;

            uint32_t ahi[2][4], alo[2][4];
#pragma unroll
            for (int mi = 0; mi < 2; mi++) {
                ldsm4(ahi[mi], st + arow[mi] + cb);
                ldsm4(alo[mi], st + GTILE_B + arow[mi] + cb);
            }
            uint32_t rh[4][4];
#pragma unroll
            for (int j = 0; j < 4; j++)
                ldsm4(rh[j], st + 2 * GTILE_B + wrow[j] + cb);

            // hi pass (reuse distance 16)
#pragma unroll
            for (int j = 0; j < 4; j++) {
                uint32_t bh0[2] = { rh[j][0], rh[j][2] }, bh1[2] = { rh[j][1], rh[j][3] };
#pragma unroll
                for (int mi = 0; mi < 2; mi++) {
                    mma16816(acc[mi][2 * j],     ahi[mi], bh0);
                    mma16816(acc[mi][2 * j + 1], ahi[mi], bh1);
                }
            }
            // lo pass
#pragma unroll
            for (int j = 0; j < 4; j++) {
                uint32_t bh0[2] = { rh[j][0], rh[j][2] }, bh1[2] = { rh[j][1], rh[j][3] };
#pragma unroll
                for (int mi = 0; mi < 2; mi++) {
                    mma16816(acc[mi][2 * j],     alo[mi], bh0);
                    mma16816(acc[mi][2 * j + 1], alo[mi], bh1);
                }
            }
        }
    }

    const int rbase = bm + wm * 32 + (lid >> 2);
    const int cbase = bn + wn * 64 + (lid & 3) * 2;
    float* out = (z == 0) ? ar.o0 : ((z == 1) ? ar.o1 : ar.o2);

    if (out) {
#pragma unroll
        for (int mi = 0; mi < 2; mi++) {
#pragma unroll
            for (int ni = 0; ni < 8; ni++) {
                int col = cbase + ni * 8;
                float bx = bias[col], by = bias[col + 1];
                int r0 = rbase + mi * 16;
                float2 v0 = make_float2((acc[mi][ni][0] + bx) * scale, (acc[mi][ni][1] + by) * scale);
                float2 v1 = make_float2((acc[mi][ni][2] + bx) * scale, (acc[mi][ni][3] + by) * scale);
                *(float2*)(out + (size_t)r0 * DM + col) = v0;
                *(float2*)(out + (size_t)(r0 + 8) * DM + col) = v1;
            }
        }
    } else {
        __half* ohi = (z == 0) ? ar.ohi0 : ((z == 1) ? ar.ohi1 : ar.ohi2);
        __half* olo = (z == 0) ? ar.olo0 : ((z == 1) ? ar.olo1 : ar.olo2);
#pragma unroll
        for (int mi = 0; mi < 2; mi++) {
#pragma unroll
            for (int ni = 0; ni < 8; ni++) {
                int col = cbase + ni * 8;
                float bx = bias[col], by = bias[col + 1];
                int r0 = rbase + mi * 16;
                float v00 = (acc[mi][ni][0] + bx) * scale, v01 = (acc[mi][ni][1] + by) * scale;
                float v10 = (acc[mi][ni][2] + bx) * scale, v11 = (acc[mi][ni][3] + by) * scale;
                __half2 h0 = __floats2half2_rn(v00, v01);
                __half2 h1 = __floats2half2_rn(v10, v11);
                size_t p0 = (size_t)r0 * DM + col;
                size_t p1 = (size_t)(r0 + 8) * DM + col;
                *(__half2*)(ohi + p0) = h0;
                *(__half2*)(ohi + p1) = h1;
                if (olo) {
                    float2 f0 = __half22float2(h0);
                    float2 f1 = __half22float2(h1);
                    *(__half2*)(olo + p0) = __floats2half2_rn(v00 - f0.x, v01 - f0.y);
                    *(__half2*)(olo + p1) = __floats2half2_rn(v10 - f1.x, v11 - f1.y);
                }
            }
        }
    }
}

// ---------------------------------------------------------------------------
// Tensor-core flash attention — unchanged from R14 (kg-outer QK, fp16 P)
// ---------------------------------------------------------------------------
#define AKV_BASE 32768
#define AKV_STAGE 32768
#define ATTN_SMEM (32768 + 2 * AKV_STAGE + 1024)

__global__ __launch_bounds__(256) void attn_mma()
{
    extern __shared__ char sm_raw[];
    const uint32_t sraw = smem_u32(sm_raw);
    const uint32_t sbase = (sraw + 1023u) & ~1023u;

    const int tid = threadIdx.x;
    const int wid = tid >> 5;
    const int lid = tid & 31;
    const int b = blockIdx.z;
    const int h = blockIdx.y;
    const int q0 = blockIdx.x * 128;

#pragma unroll
    for (int i = 0; i < 8; i++) {
        int s = tid + 256 * i;
        int buf = s >> 10;
        int r = (s & 1023) >> 3;
        int sg = s & 7;
        uint32_t off = ((uint32_t)(r * 128 + sg * 16)) ^ (((uint32_t)(r & 7)) << 4);
        const __half* src = (buf ? g_qlo : g_qhi) + (size_t)(b * SEQ + q0 + r) * DM + h * DKH + sg * 8;
        cp_async16(sbase + (uint32_t)buf * 16384 + off, src);
    }
    cp_commit();

    auto issue_kv = [&](int t, int stg) {
        const int kv0 = t * 128;
        const uint32_t stb = sbase + AKV_BASE + (uint32_t)stg * AKV_STAGE;
#pragma unroll
        for (int i = 0; i < 8; i++) {
            int s = tid + 256 * i;
            int buf = s >> 10;
            int r = (s & 1023) >> 3;
            int sg = s & 7;
            uint32_t off = ((uint32_t)(r * 128 + sg * 16)) ^ (((uint32_t)(r & 7)) << 4);
            const __half* base = buf ? g_vhi : g_khi;
            cp_async16(stb + (uint32_t)buf * 16384 + off,
                       base + (size_t)(b * SEQ + kv0 + r) * DM + h * DKH + sg * 8);
        }
    };

    issue_kv(0, 0); cp_commit();

    const int lm_row = (lid & 7) + 8 * ((lid >> 3) & 1);
    const uint32_t rbyte = (uint32_t)(lm_row * 128);
    const uint32_t lsw = ((uint32_t)(lm_row & 7)) << 4;
    const uint32_t cpick = (uint32_t)(16 * (lid >> 4));

    cp_wait1();
    __syncthreads();
    uint32_t aq_hi[4][4], aq_lo[4][4];
    {
        uint32_t qb_hi = sbase + (uint32_t)(wid * 2048) + rbyte;
        uint32_t qb_lo = qb_hi + 16384;
#pragma unroll
        for (int kg = 0; kg < 4; kg++) {
            uint32_t cb = (cpick + kg * 32) ^ lsw;
            ldsm4(aq_hi[kg], qb_hi + cb);
            ldsm4(aq_lo[kg], qb_lo + cb);
        }
    }

    float m0 = -1e30f, m1 = -1e30f;
    float acc_l[4];
    float acc_o[8][4];
#pragma unroll
    for (int j = 0; j < 4; j++) acc_l[j] = 0.0f;
#pragma unroll
    for (int n = 0; n < 8; n++)
#pragma unroll
        for (int j = 0; j < 4; j++) acc_o[n][j] = 0.0f;

    const uint32_t ones2[2] = { 0x3C003C00u, 0x3C003C00u };

    for (int t = 0; t < SEQ / 128; t++) {
        cp_wait0();
        __syncthreads();

        if (t + 1 < SEQ / 128) { issue_kv(t + 1, (t + 1) & 1); cp_commit(); }

        const uint32_t stb = sbase + AKV_BASE + (uint32_t)(t & 1) * AKV_STAGE;
        const uint32_t kb = stb + rbyte;
        const uint32_t vb = kb + 16384;

        float c[16][4];
#pragma unroll
        for (int j = 0; j < 16; j++)
#pragma unroll
            for (int q = 0; q < 4; q++) c[j][q] = 0.0f;

#pragma unroll
        for (int kg = 0; kg < 4; kg++) {
            const uint32_t cb = (cpick + kg * 32) ^ lsw;
#pragma unroll
            for (int half = 0; half < 2; half++) {
                uint32_t rh[4][4];
#pragma unroll
                for (int jj = 0; jj < 4; jj++)
                    ldsm4(rh[jj], kb + (uint32_t)((half * 4 + jj) * 2048) + cb);
#pragma unroll
                for (int jj = 0; jj < 4; jj++) {
                    int j2 = half * 4 + jj;
                    uint32_t bh0[2] = { rh[jj][0], rh[jj][2] }, bh1[2] = { rh[jj][1], rh[jj][3] };
                    mma16816(c[2 * j2],     aq_hi[kg], bh0);
                    mma16816(c[2 * j2 + 1], aq_hi[kg], bh1);
                }
#pragma unroll
                for (int jj = 0; jj < 4; jj++) {
                    int j2 = half * 4 + jj;
                    uint32_t bh0[2] = { rh[jj][0], rh[jj][2] }, bh1[2] = { rh[jj][1], rh[jj][3] };
                    mma16816(c[2 * j2],     aq_lo[kg], bh0);
                    mma16816(c[2 * j2 + 1], aq_lo[kg], bh1);
                }
            }
        }

        float mx0 = -1e30f, mx1 = -1e30f;
#pragma unroll
        for (int j = 0; j < 16; j++) {
            mx0 = fmaxf(mx0, fmaxf(c[j][0], c[j][1]));
            mx1 = fmaxf(mx1, fmaxf(c[j][2], c[j][3]));
        }
        mx0 = fmaxf(mx0, __shfl_xor_sync(0xffffffffu, mx0, 1));
        mx0 = fmaxf(mx0, __shfl_xor_sync(0xffffffffu, mx0, 2));
        mx1 = fmaxf(mx1, __shfl_xor_sync(0xffffffffu, mx1, 1));
        mx1 = fmaxf(mx1, __shfl_xor_sync(0xffffffffu, mx1, 2));

        float mn0 = fmaxf(m0, mx0), mn1 = fmaxf(m1, mx1);
        float al0 = ex2f(m0 - mn0), al1 = ex2f(m1 - mn1);
        m0 = mn0; m1 = mn1;

        acc_l[0] *= al0; acc_l[1] *= al0;
        acc_l[2] *= al1; acc_l[3] *= al1;
#pragma unroll
        for (int n = 0; n < 8; n++) {
            acc_o[n][0] *= al0; acc_o[n][1] *= al0;
            acc_o[n][2] *= al1; acc_o[n][3] *= al1;
        }

        uint32_t ph[16][2];
#pragma unroll
        for (int j = 0; j < 16; j++) {
            ph[j][0] = ex2_h2(h2u(__floats2half2_rn(c[j][0] - mn0, c[j][1] - mn0)));
            ph[j][1] = ex2_h2(h2u(__floats2half2_rn(c[j][2] - mn1, c[j][3] - mn1)));
        }

#pragma unroll
        for (int kg = 0; kg < 8; kg++) {
            uint32_t A[4] = { ph[2 * kg][0], ph[2 * kg][1], ph[2 * kg + 1][0], ph[2 * kg + 1][1] };

            mma16816(acc_l, A, ones2);

            const uint32_t kvoff = (uint32_t)(kg * 2048);
#pragma unroll
            for (int d2 = 0; d2 < 4; d2++) {
                uint32_t cb = (cpick + d2 * 32) ^ lsw;
                uint32_t rhv[4];
                ldsm4t(rhv, vb + kvoff + cb);
                uint32_t bh0[2] = { rhv[0], rhv[1] }, bh1[2] = { rhv[2], rhv[3] };
                mma16816(acc_o[2 * d2],     A, bh0);
                mma16816(acc_o[2 * d2 + 1], A, bh1);
            }
        }
    }

    const float inv0 = 1.0f / acc_l[0];
    const float inv1 = 1.0f / acc_l[2];
    const int gr0 = q0 + wid * 16 + (lid >> 2);
    const int gr1 = gr0 + 8;
    const int colb = h * DKH + (lid & 3) * 2;
#pragma unroll
    for (int n = 0; n < 8; n++) {
        int col = colb + n * 8;
        size_t o0 = (size_t)(b * SEQ + gr0) * DM + col;
        size_t o1 = (size_t)(b * SEQ + gr1) * DM + col;
        float vx0 = acc_o[n][0] * inv0, vy0 = acc_o[n][1] * inv0;
        float vx1 = acc_o[n][2] * inv1, vy1 = acc_o[n][3] * inv1;
        __half2 h0 = __floats2half2_rn(vx0, vy0);
        __half2 h1 = __floats2half2_rn(vx1, vy1);
        float2 f0 = __half22float2(h0);
        float2 f1 = __half22float2(h1);
        *(__half2*)(g_chi + o0) = h0;
        *(__half2*)(g_chi + o1) = h1;
        *(__half2*)(g_clo + o0) = __floats2half2_rn(vx0 - f0.x, vy0 - f0.y);
        *(__half2*)(g_clo + o1) = __floats2half2_rn(vx1 - f1.x, vy1 - f1.y);
    }
}

// ---------------------------------------------------------------------------
#define QSCALE 0.18033688f   // (1/8) * log2(e)

extern "C" void kernel_launch(void* const* d_in, const int* in_sizes, int n_in,
                              void* d_out, int out_size)
{
    const float* query = (const float*)d_in[0];
    const float* key   = (const float*)d_in[1];
    const float* value = (const float*)d_in[2];
    const float* Wq    = (const float*)d_in[3];
    const float* bq    = (const float*)d_in[4];
    const float* Wk    = (const float*)d_in[5];
    const float* bk    = (const float*)d_in[6];
    const float* Wv    = (const float*)d_in[7];
    const float* bv    = (const float*)d_in[8];
    const float* Wo    = (const float*)d_in[9];
    const float* bo    = (const float*)d_in[10];

    __half *xhi, *xlo, *whi, *chi, *clo;
    __half *qhi, *qlo, *khi, *vhi;
    cudaGetSymbolAddress((void**)&xhi, g_xhi);
    cudaGetSymbolAddress((void**)&xlo, g_xlo);
    cudaGetSymbolAddress((void**)&whi, g_whi);
    cudaGetSymbolAddress((void**)&chi, g_chi);
    cudaGetSymbolAddress((void**)&clo, g_clo);
    cudaGetSymbolAddress((void**)&qhi, g_qhi);
    cudaGetSymbolAddress((void**)&qlo, g_qlo);
    cudaGetSymbolAddress((void**)&khi, g_khi);
    cudaGetSymbolAddress((void**)&vhi, g_vhi);

    cudaFuncSetAttribute(gemm_tc, cudaFuncAttributeMaxDynamicSharedMemorySize, GEMM_SMEM);
    cudaFuncSetAttribute(attn_mma, cudaFuncAttributeMaxDynamicSharedMemorySize, ATTN_SMEM);

    const size_t XN = (size_t)MTOK * DM;
    const size_t WN = (size_t)DM * DM;

    ConvArgs ca;
    ca.x0 = query; ca.x1 = key; ca.x2 = value;
    ca.w0 = Wq; ca.w1 = Wk; ca.w2 = Wv; ca.w3 = Wo;
    ca.xhi = xhi; ca.xlo = xlo; ca.whi = whi;
    convert_all<<<CONV_TOTAL / 256, 256>>>(ca);

    GemmArgs qkv;
    qkv.xhi = xhi; qkv.xlo = xlo; qkv.whi = whi;
    qkv.b0 = bq; qkv.b1 = bk; qkv.b2 = bv;
    qkv.o0 = nullptr; qkv.o1 = nullptr; qkv.o2 = nullptr;
    qkv.ohi0 = qhi; qkv.olo0 = qlo;
    qkv.ohi1 = khi; qkv.olo1 = nullptr;
    qkv.ohi2 = vhi; qkv.olo2 = nullptr;
    qkv.s0 = QSCALE; qkv.s1 = 1.0f; qkv.s2 = 1.0f;
    qkv.xstride = (long long)XN; qkv.wstride = (long long)WN;
    gemm_tc<<<dim3(DM / 128, MTOK / 128, 3), 256, GEMM_SMEM>>>(qkv);

    attn_mma<<<dim3(SEQ / 128, NH, NB), 256, ATTN_SMEM>>>();

    GemmArgs og;
    og.xhi = chi; og.xlo = clo; og.whi = whi + 3 * WN;
    og.b0 = bo; og.b1 = bo; og.b2 = bo;
    og.o0 = (float*)d_out; og.o1 = (float*)d_out; og.o2 = (float*)d_out;
    og.ohi0 = nullptr; og.olo0 = nullptr; og.ohi1 = nullptr; og.olo1 = nullptr;
    og.ohi2 = nullptr; og.olo2 = nullptr;
    og.s0 = 1.0f; og.s1 = 1.0f; og.s2 = 1.0f;
    og.xstride = 0; og.wstride = 0;
    gemm_tc<<<dim3(DM / 128, MTOK / 128, 1), 256, GEMM_SMEM>>>(og);
}